// round 1
// baseline (speedup 1.0000x reference)
#include <cuda_runtime.h>

#define NF   50
#define DIM  64
#define ATT  64
#define CARDI 10000
#define NPAIR 1225
#define NTHREADS 256

__device__ __forceinline__ void ffma2(unsigned long long &acc,
                                      unsigned long long a,
                                      unsigned long long b) {
    asm("fma.rn.f32x2 %0, %1, %2, %0;" : "+l"(acc) : "l"(a), "l"(b));
}

__global__ __launch_bounds__(NTHREADS, 2)
void afm_kernel(const int* __restrict__ x32,
                const float* __restrict__ emb,
                const float* __restrict__ W1,
                const float* __restrict__ b1,
                const float* __restrict__ w2,
                const float* __restrict__ b2,
                const float* __restrict__ lin_w,
                const float* __restrict__ lin_b,
                float* __restrict__ out)
{
    __shared__ __align__(16) float sF[NF * 65];     // padded: bank-conflict-free lane-divergent reads
    __shared__ __align__(16) float sW[DIM * ATT];   // W1[d][a] row-major
    __shared__ float sb1[ATT], sw2[ATT];
    __shared__ float slog[NPAIR], ssum[NPAIR];
    __shared__ float sLinA[64];
    __shared__ float sRed[32];
    __shared__ float sM;

    const int b   = blockIdx.x;
    const int tid = threadIdx.x;

    // x may be int32 or int64 depending on JAX x64 config; values < 500000 so
    // int64 little-endian has zero high words. Probe a few odd int32 slots.
    const bool is64 = (x32[1] == 0) & (x32[3] == 0) & (x32[5] == 0) & (x32[7] == 0);
    const long long* x64 = (const long long*)x32;

    // ---- Phase A: stage inputs ----
    for (int q = tid; q < NF * DIM / 4; q += NTHREADS) {   // 800 float4
        int row = q >> 4;          // 16 float4 per embedding row
        int c4  = q & 15;
        long long xv = is64 ? x64[(long long)b * NF + row]
                            : (long long)x32[b * NF + row];
        int gidx = (int)xv + row * CARDI;
        float4 v = ((const float4*)(emb + (long long)gidx * DIM))[c4];
        float* dst = sF + row * 65 + c4 * 4;
        dst[0] = v.x; dst[1] = v.y; dst[2] = v.z; dst[3] = v.w;
    }
    for (int q = tid; q < DIM * ATT / 4; q += NTHREADS)
        ((float4*)sW)[q] = ((const float4*)W1)[q];
    if (tid < ATT) { sb1[tid] = b1[tid]; sw2[tid] = w2[tid]; }
    if (tid < 64) sLinA[tid] = 0.0f;
    if (tid < NF) {
        long long xv = is64 ? x64[(long long)b * NF + tid]
                            : (long long)x32[b * NF + tid];
        int gidx = (int)xv + tid * CARDI;
        sLinA[tid] = lin_w[gidx];
    }
    __syncthreads();

    // ---- Phase B: one pair per thread, full h[64] in packed f32x2 registers ----
    for (int p = tid; p < NPAIR; p += NTHREADS) {
        // decode p -> (i, j), i < j, row-major triu(k=1); base(i) = i*(99-i)/2
        int i = (int)((99.0f - sqrtf(9801.0f - 8.0f * (float)p)) * 0.5f);
        i = min(max(i, 0), 48);
        while (i * (99 - i) / 2 > p) --i;
        while ((i + 1) * (98 - i) / 2 <= p) ++i;
        int j = i + 1 + (p - i * (99 - i) / 2);

        const float* fi = sF + i * 65;
        const float* fj = sF + j * 65;

        unsigned long long h2[32];
        #pragma unroll
        for (int k = 0; k < 32; k++) h2[k] = 0ull;
        float s0 = 0.0f, s1 = 0.0f;

        #pragma unroll 2
        for (int d = 0; d < DIM; d++) {
            float v = fi[d] * fj[d];
            if (d & 1) s1 += v; else s0 += v;
            unsigned long long vv;
            asm("mov.b64 %0, {%1, %2};" : "=l"(vv) : "f"(v), "f"(v));
            const ulonglong2* wrow = (const ulonglong2*)(sW + d * ATT);
            #pragma unroll
            for (int k2 = 0; k2 < 16; k2++) {
                ulonglong2 w = wrow[k2];           // LDS.128 broadcast (same addr warp-wide)
                ffma2(h2[2 * k2],     vv, w.x);
                ffma2(h2[2 * k2 + 1], vv, w.y);
            }
        }

        // per-pair epilogue: relu -> dot(w2). b2 is a uniform logit shift -> softmax-invariant.
        float logit = 0.0f;
        #pragma unroll
        for (int k = 0; k < 32; k++) {
            float lo, hi;
            asm("mov.b64 {%0, %1}, %2;" : "=f"(lo), "=f"(hi) : "l"(h2[k]));
            lo = fmaxf(lo + sb1[2 * k],     0.0f);
            hi = fmaxf(hi + sb1[2 * k + 1], 0.0f);
            logit = fmaf(lo, sw2[2 * k],     logit);
            logit = fmaf(hi, sw2[2 * k + 1], logit);
        }
        slog[p] = logit;
        ssum[p] = s0 + s1;
    }
    __syncthreads();

    // ---- Phase C: softmax over pairs + combine ----
    float m = -1e30f;
    for (int p = tid; p < NPAIR; p += NTHREADS) m = fmaxf(m, slog[p]);
    #pragma unroll
    for (int o = 16; o; o >>= 1) m = fmaxf(m, __shfl_xor_sync(0xffffffffu, m, o));
    if ((tid & 31) == 0) sRed[tid >> 5] = m;
    __syncthreads();
    if (tid < 32) {
        float t = (tid < NTHREADS / 32) ? sRed[tid] : -1e30f;
        #pragma unroll
        for (int o = 4; o; o >>= 1) t = fmaxf(t, __shfl_xor_sync(0xffffffffu, t, o));
        if (tid == 0) sM = t;
    }
    __syncthreads();
    const float M = sM;

    float es = 0.0f, ws = 0.0f;
    for (int p = tid; p < NPAIR; p += NTHREADS) {
        float e = __expf(slog[p] - M);
        es += e;
        ws = fmaf(e, ssum[p], ws);
    }
    #pragma unroll
    for (int o = 16; o; o >>= 1) {
        es += __shfl_xor_sync(0xffffffffu, es, o);
        ws += __shfl_xor_sync(0xffffffffu, ws, o);
    }
    if ((tid & 31) == 0) { sRed[tid >> 5] = es; sRed[16 + (tid >> 5)] = ws; }
    __syncthreads();
    if (tid == 0) {
        float ES = 0.0f, WS = 0.0f;
        #pragma unroll
        for (int w = 0; w < NTHREADS / 32; w++) { ES += sRed[w]; WS += sRed[16 + w]; }
        float lin = lin_b[0];
        #pragma unroll
        for (int f = 0; f < NF; f++) lin += sLinA[f];
        out[b] = lin + WS / ES;
    }
}

extern "C" void kernel_launch(void* const* d_in, const int* in_sizes, int n_in,
                              void* d_out, int out_size)
{
    const int*   x     = (const int*)d_in[0];
    const float* emb   = (const float*)d_in[1];
    const float* W1    = (const float*)d_in[2];
    const float* b1    = (const float*)d_in[3];
    const float* w2    = (const float*)d_in[4];
    const float* b2    = (const float*)d_in[5];
    const float* lin_w = (const float*)d_in[6];
    const float* lin_b = (const float*)d_in[7];
    float* out = (float*)d_out;

    afm_kernel<<<out_size, NTHREADS>>>(x, emb, W1, b1, w2, b2, lin_w, lin_b, out);
}

// round 2
// speedup vs baseline: 1.6314x; 1.6314x over previous
#include <cuda_runtime.h>

#define NF    50
#define DIM   64
#define ATT   64
#define CARDI 10000
#define NPAIR 1225
#define NTHREADS 256
#define MTILE 128
#define NTILES ((NPAIR + MTILE - 1) / MTILE)   // 10
#define IST   132                               // sI row stride (floats), 16B-aligned

// ---- dynamic smem layout (floats unless noted) ----
// sW   [4096]            W1[d][a]
// sF   [50*65]           embeddings, padded rows
// slog [1225]
// ssum [1225]
// sSumP[256]             per-(row,half) inter_sum partials
// si/sj uchar[1232] each pair decode tables
// sI   [64*IST]          inter tile, d-major  (aliased by sP[128*17] in epilogue)
#define OFF_W    0
#define OFF_F    (OFF_W + DIM*ATT)
#define OFF_LOG  (OFF_F + NF*65)
#define OFF_SUM  (OFF_LOG + NPAIR)
#define OFF_SP   (OFF_SUM + NPAIR)
#define OFF_END_F (OFF_SP + 256)
#define OFF_SI_B  (OFF_END_F * 4)              // byte offset of si table
#define OFF_SJ_B  (OFF_SI_B + 1232)
#define OFF_I_B   (((OFF_SJ_B + 1232) + 15) & ~15)  // byte offset of sI (16B aligned)
#define SMEM_BYTES (OFF_I_B + DIM*IST*4)

__device__ __forceinline__ void ffma2(unsigned long long &acc,
                                      unsigned long long a,
                                      unsigned long long b) {
    asm("fma.rn.f32x2 %0, %1, %2, %0;" : "+l"(acc) : "l"(a), "l"(b));
}
__device__ __forceinline__ unsigned long long dup2(float v) {
    unsigned long long r;
    asm("mov.b64 %0, {%1, %1};" : "=l"(r) : "f"(v));
    return r;
}

__global__ __launch_bounds__(NTHREADS, 2)
void afm_kernel(const int* __restrict__ x32,
                const float* __restrict__ emb,
                const float* __restrict__ W1,
                const float* __restrict__ b1,
                const float* __restrict__ w2,
                const float* __restrict__ b2,
                const float* __restrict__ lin_w,
                const float* __restrict__ lin_b,
                float* __restrict__ out)
{
    extern __shared__ __align__(16) char smem[];
    float* sW   = (float*)smem + OFF_W;
    float* sF   = (float*)smem + OFF_F;
    float* slog = (float*)smem + OFF_LOG;
    float* ssum = (float*)smem + OFF_SUM;
    float* sSumP= (float*)smem + OFF_SP;
    unsigned char* si = (unsigned char*)(smem + OFF_SI_B);
    unsigned char* sj = (unsigned char*)(smem + OFF_SJ_B);
    float* sI   = (float*)(smem + OFF_I_B);
    float* sP   = sI;                      // alias: used only after GEMM reads finish

    __shared__ float sb1[ATT], sw2[ATT], sLinA[64], sRed[32], sM;

    const int b   = blockIdx.x;
    const int tid = threadIdx.x;

    // int32 vs int64 index dtype probe (values < 5e5 -> int64 high words zero)
    const bool is64 = (x32[1] == 0) & (x32[3] == 0) & (x32[5] == 0) & (x32[7] == 0);
    const long long* x64 = (const long long*)x32;

    // ---- Phase A: stage inputs ----
    for (int q = tid; q < NF * DIM / 4; q += NTHREADS) {
        int row = q >> 4;
        int c4  = q & 15;
        long long xv = is64 ? x64[(long long)b * NF + row]
                            : (long long)x32[b * NF + row];
        int gidx = (int)xv + row * CARDI;
        float4 v = ((const float4*)(emb + (long long)gidx * DIM))[c4];
        float* dst = sF + row * 65 + c4 * 4;
        dst[0] = v.x; dst[1] = v.y; dst[2] = v.z; dst[3] = v.w;
    }
    for (int q = tid; q < DIM * ATT / 4; q += NTHREADS)
        ((float4*)sW)[q] = ((const float4*)W1)[q];
    if (tid < ATT) { sb1[tid] = b1[tid]; sw2[tid] = w2[tid]; }
    if (tid < 64) sLinA[tid] = 0.0f;
    if (tid < NF) {
        long long xv = is64 ? x64[(long long)b * NF + tid]
                            : (long long)x32[b * NF + tid];
        sLinA[tid] = lin_w[(int)xv + tid * CARDI];
    }
    // pair decode tables
    for (int p = tid; p < NPAIR; p += NTHREADS) {
        int i = (int)((99.0f - sqrtf(9801.0f - 8.0f * (float)p)) * 0.5f);
        i = min(max(i, 0), 48);
        while (i * (99 - i) / 2 > p) --i;
        while ((i + 1) * (98 - i) / 2 <= p) ++i;
        si[p] = (unsigned char)i;
        sj[p] = (unsigned char)(i + 1 + (p - i * (99 - i) / 2));
    }
    __syncthreads();

    // thread geometry for GEMM: 4 cols (cg), 8 rows (rg)
    const int cg = tid & 15;         // column group: cols 4*cg..4*cg+3
    const int rg = tid >> 4;         // row group:    rows 8*rg..8*rg+7

    // ---- tiles of 128 pairs ----
    for (int t = 0; t < NTILES; t++) {
        const int p0 = t * MTILE;

        // -- materialize inter tile, transposed sI[d][r], + inter_sum partials --
        {
            int r  = tid & 127;
            int dh = tid >> 7;            // 0/1 -> d in [32*dh, 32*dh+32)
            int p  = p0 + r;
            if (p < NPAIR) {
                const float* fi = sF + si[p] * 65;
                const float* fj = sF + sj[p] * 65;
                float s = 0.0f;
                #pragma unroll 8
                for (int dd = 0; dd < 32; dd++) {
                    int d = dh * 32 + dd;
                    float v = fi[d] * fj[d];
                    s += v;
                    sI[d * IST + r] = v;
                }
                sSumP[r * 2 + dh] = s;
            } else {
                #pragma unroll 8
                for (int dd = 0; dd < 32; dd++)
                    sI[(dh * 32 + dd) * IST + r] = 0.0f;
                sSumP[r * 2 + dh] = 0.0f;
            }
        }
        __syncthreads();

        // -- register-blocked GEMM: h_pre(8 rows x 4 cols) --
        unsigned long long acc[16];
        #pragma unroll
        for (int k = 0; k < 16; k++) acc[k] = 0ull;

        const float* Abase = sI + 8 * rg;
        const float* Bbase = sW + 4 * cg;
        #pragma unroll 16
        for (int d = 0; d < DIM; d++) {
            ulonglong2 a0 = *(const ulonglong2*)(Abase + d * IST);      // rows 0..3 (2 f32x2)
            ulonglong2 a1 = *(const ulonglong2*)(Abase + d * IST + 4);  // rows 4..7
            float4 bv = *(const float4*)(Bbase + d * ATT);
            unsigned long long b0 = dup2(bv.x), b1d = dup2(bv.y),
                               b2d = dup2(bv.z), b3 = dup2(bv.w);
            ffma2(acc[ 0], a0.x, b0);  ffma2(acc[ 1], a0.x, b1d);
            ffma2(acc[ 2], a0.x, b2d); ffma2(acc[ 3], a0.x, b3);
            ffma2(acc[ 4], a0.y, b0);  ffma2(acc[ 5], a0.y, b1d);
            ffma2(acc[ 6], a0.y, b2d); ffma2(acc[ 7], a0.y, b3);
            ffma2(acc[ 8], a1.x, b0);  ffma2(acc[ 9], a1.x, b1d);
            ffma2(acc[10], a1.x, b2d); ffma2(acc[11], a1.x, b3);
            ffma2(acc[12], a1.y, b0);  ffma2(acc[13], a1.y, b1d);
            ffma2(acc[14], a1.y, b2d); ffma2(acc[15], a1.y, b3);
        }
        __syncthreads();   // all GEMM reads of sI done before sP (alias) writes

        // -- epilogue: relu + dot(w2) partials over this thread's 4 cols --
        {
            float pl[8];
            #pragma unroll
            for (int rr = 0; rr < 8; rr++) pl[rr] = 0.0f;
            #pragma unroll
            for (int rp = 0; rp < 4; rp++) {
                #pragma unroll
                for (int c = 0; c < 4; c++) {
                    float lo, hi;
                    asm("mov.b64 {%0, %1}, %2;" : "=f"(lo), "=f"(hi) : "l"(acc[rp * 4 + c]));
                    int col = 4 * cg + c;
                    lo = fmaxf(lo + sb1[col], 0.0f);
                    hi = fmaxf(hi + sb1[col], 0.0f);
                    pl[2 * rp]     = fmaf(lo, sw2[col], pl[2 * rp]);
                    pl[2 * rp + 1] = fmaf(hi, sw2[col], pl[2 * rp + 1]);
                }
            }
            #pragma unroll
            for (int rr = 0; rr < 8; rr++)
                sP[(8 * rg + rr) * 17 + cg] = pl[rr];
        }
        __syncthreads();

        // -- reduce partials -> logits, inter_sum --
        if (tid < MTILE) {
            int p = p0 + tid;
            if (p < NPAIR) {
                float lg = 0.0f;
                #pragma unroll
                for (int c = 0; c < 16; c++) lg += sP[tid * 17 + c];
                slog[p] = lg;
                ssum[p] = sSumP[tid * 2] + sSumP[tid * 2 + 1];
            }
        }
        __syncthreads();
    }

    // ---- Phase C: softmax over pairs + combine ----
    float m = -1e30f;
    for (int p = tid; p < NPAIR; p += NTHREADS) m = fmaxf(m, slog[p]);
    #pragma unroll
    for (int o = 16; o; o >>= 1) m = fmaxf(m, __shfl_xor_sync(0xffffffffu, m, o));
    if ((tid & 31) == 0) sRed[tid >> 5] = m;
    __syncthreads();
    if (tid < 32) {
        float tv = (tid < NTHREADS / 32) ? sRed[tid] : -1e30f;
        #pragma unroll
        for (int o = 4; o; o >>= 1) tv = fmaxf(tv, __shfl_xor_sync(0xffffffffu, tv, o));
        if (tid == 0) sM = tv;
    }
    __syncthreads();
    const float M = sM;

    float es = 0.0f, ws = 0.0f;
    for (int p = tid; p < NPAIR; p += NTHREADS) {
        float e = __expf(slog[p] - M);
        es += e;
        ws = fmaf(e, ssum[p], ws);
    }
    #pragma unroll
    for (int o = 16; o; o >>= 1) {
        es += __shfl_xor_sync(0xffffffffu, es, o);
        ws += __shfl_xor_sync(0xffffffffu, ws, o);
    }
    if ((tid & 31) == 0) { sRed[tid >> 5] = es; sRed[16 + (tid >> 5)] = ws; }
    __syncthreads();
    if (tid == 0) {
        float ES = 0.0f, WS = 0.0f;
        #pragma unroll
        for (int w = 0; w < NTHREADS / 32; w++) { ES += sRed[w]; WS += sRed[16 + w]; }
        float lin = lin_b[0];
        #pragma unroll
        for (int f = 0; f < NF; f++) lin += sLinA[f];
        out[b] = lin + WS / ES;
    }
}

extern "C" void kernel_launch(void* const* d_in, const int* in_sizes, int n_in,
                              void* d_out, int out_size)
{
    const int*   x     = (const int*)d_in[0];
    const float* emb   = (const float*)d_in[1];
    const float* W1    = (const float*)d_in[2];
    const float* b1    = (const float*)d_in[3];
    const float* w2    = (const float*)d_in[4];
    const float* b2    = (const float*)d_in[5];
    const float* lin_w = (const float*)d_in[6];
    const float* lin_b = (const float*)d_in[7];
    float* out = (float*)d_out;

    static int configured = 0;
    if (!configured) {
        cudaFuncSetAttribute(afm_kernel, cudaFuncAttributeMaxDynamicSharedMemorySize,
                             SMEM_BYTES);
        configured = 1;
    }
    afm_kernel<<<out_size, NTHREADS, SMEM_BYTES>>>(x, emb, W1, b1, w2, b2,
                                                   lin_w, lin_b, out);
}

// round 4
// speedup vs baseline: 4.5710x; 2.8018x over previous
#include <cuda_runtime.h>
#include <cuda_bf16.h>

#define NF    50
#define DIM   64
#define ATT   64
#define CARDI 10000
#define NPAIR 1225
#define NTHREADS 256
#define MTILE 128
#define NTILES 10
#define FST   68          // sF row stride (floats)
#define BST   144         // bf16 tile row stride in BYTES (pad: conflict-free ldmatrix)

// ---- dynamic smem byte offsets ----
#define OFF_A    0                       // A tile: 128 rows x 144B
#define OFF_B    (128 * BST)             // B = W1^T: 64 rows x 144B
#define OFF_F    (OFF_B + 64 * BST)      // sF fp32 50*68
#define OFF_LOG  (OFF_F + NF * FST * 4)
#define OFF_SUM  (OFF_LOG + NPAIR * 4)
#define OFF_SP   (OFF_SUM + NPAIR * 4)
#define OFF_SI   (OFF_SP + 256 * 4)
#define OFF_SJ   (OFF_SI + 1232)
#define SMEM_DYN (OFF_SJ + 1232)

__device__ __forceinline__ unsigned smem_u32(const void* p) {
    unsigned a;
    asm("{ .reg .u64 t; cvta.to.shared.u64 t, %1; cvt.u32.u64 %0, t; }"
        : "=r"(a) : "l"(p));
    return a;
}
__device__ __forceinline__ unsigned bf2(float lo, float hi) {
    unsigned r;
    asm("cvt.rn.bf16x2.f32 %0, %1, %2;" : "=r"(r) : "f"(hi), "f"(lo));
    return r;
}
__device__ __forceinline__ void ldsm4(unsigned& r0, unsigned& r1,
                                      unsigned& r2, unsigned& r3, unsigned addr) {
    asm volatile("ldmatrix.sync.aligned.m8n8.x4.shared.b16 {%0,%1,%2,%3}, [%4];"
                 : "=r"(r0), "=r"(r1), "=r"(r2), "=r"(r3) : "r"(addr));
}
__device__ __forceinline__ void mma16816(float4& d,
                                         unsigned a0, unsigned a1, unsigned a2, unsigned a3,
                                         unsigned b0, unsigned b1) {
    asm volatile(
        "mma.sync.aligned.m16n8k16.row.col.f32.bf16.bf16.f32 "
        "{%0,%1,%2,%3}, {%4,%5,%6,%7}, {%8,%9}, {%0,%1,%2,%3};"
        : "+f"(d.x), "+f"(d.y), "+f"(d.z), "+f"(d.w)
        : "r"(a0), "r"(a1), "r"(a2), "r"(a3), "r"(b0), "r"(b1));
}

__global__ __launch_bounds__(NTHREADS, 3)
void afm_kernel(const int* __restrict__ x32,
                const float* __restrict__ emb,
                const float* __restrict__ W1,
                const float* __restrict__ b1,
                const float* __restrict__ w2,
                const float* __restrict__ b2,
                const float* __restrict__ lin_w,
                const float* __restrict__ lin_b,
                float* __restrict__ out)
{
    extern __shared__ __align__(16) char sb[];
    float* sF    = (float*)(sb + OFF_F);
    float* slog  = (float*)(sb + OFF_LOG);
    float* ssum  = (float*)(sb + OFF_SUM);
    float* sSumP = (float*)(sb + OFF_SP);
    unsigned char* si = (unsigned char*)(sb + OFF_SI);
    unsigned char* sj = (unsigned char*)(sb + OFF_SJ);
    const unsigned sbase = smem_u32(sb);

    __shared__ float sb1[ATT], sw2[ATT], sLinA[64], sRed[32], sM;

    const int b = blockIdx.x, tid = threadIdx.x;
    const int wid = tid >> 5, lane = tid & 31;

    // int32 vs int64 index dtype probe (values < 5e5 -> int64 high words zero)
    const bool is64 = (x32[1] == 0) & (x32[3] == 0) & (x32[5] == 0) & (x32[7] == 0);
    const long long* x64 = (const long long*)x32;

    // ---- Phase A: stage embeddings fp32, B = W1^T bf16, biases, pair tables ----
    for (int q = tid; q < NF * DIM / 4; q += NTHREADS) {
        int row = q >> 4, c4 = q & 15;
        long long xv = is64 ? x64[(long long)b * NF + row]
                            : (long long)x32[b * NF + row];
        int gidx = (int)xv + row * CARDI;
        float4 v = ((const float4*)(emb + (long long)gidx * DIM))[c4];
        *(float4*)(sF + row * FST + c4 * 4) = v;
    }
    {   // B[n][k] = W1[k][n] bf16, row stride 144B
        int n = tid & 63, kg = tid >> 6;           // kg: 16 k's
        unsigned u[8];
        #pragma unroll
        for (int e = 0; e < 8; e++) {
            float w0 = W1[(kg * 16 + 2 * e) * ATT + n];
            float w1v = W1[(kg * 16 + 2 * e + 1) * ATT + n];
            u[e] = bf2(w0, w1v);
        }
        char* dst = sb + OFF_B + n * BST + kg * 32;
        *(uint4*)(dst)      = make_uint4(u[0], u[1], u[2], u[3]);
        *(uint4*)(dst + 16) = make_uint4(u[4], u[5], u[6], u[7]);
    }
    if (tid < ATT) { sb1[tid] = b1[tid]; sw2[tid] = w2[tid]; }
    if (tid < 64) sLinA[tid] = 0.0f;
    if (tid < NF) {
        long long xv = is64 ? x64[(long long)b * NF + tid]
                            : (long long)x32[b * NF + tid];
        sLinA[tid] = lin_w[(int)xv + tid * CARDI];
    }
    for (int p = tid; p < NPAIR; p += NTHREADS) {
        int i = (int)((99.0f - sqrtf(9801.0f - 8.0f * (float)p)) * 0.5f);
        i = min(max(i, 0), 48);
        while (i * (99 - i) / 2 > p) --i;
        while ((i + 1) * (98 - i) / 2 <= p) ++i;
        si[p] = (unsigned char)i;
        sj[p] = (unsigned char)(i + 1 + (p - i * (99 - i) / 2));
    }

    const int m0   = wid * 16;                    // warp's row block
    const int g    = lane >> 2;                   // row within 8-group
    // ldmatrix address precomputes
    const unsigned aArow = sbase + OFF_A + (m0 + (lane & 15)) * BST + (lane >> 4) * 16;
    const unsigned aBrow = sbase + OFF_B + ((lane >> 4) * 8 + (lane & 7)) * BST
                                 + ((lane >> 3) & 1) * 16;

    // ---- tiles ----
    for (int t = 0; t < NTILES; t++) {
        __syncthreads();   // previous tile's MMA reads of sA done

        // -- build bf16 A tile + fp32 inter_sum partials --
        {
            int r = tid >> 1, dh = tid & 1;       // 32 k's per (r,dh)
            int p = t * MTILE + r;
            char* A = sb + OFF_A + r * BST + dh * 64;
            if (p < NPAIR) {
                const float* fi = sF + si[p] * FST + dh * 32;
                const float* fj = sF + sj[p] * FST + dh * 32;
                float s = 0.0f;
                #pragma unroll
                for (int q = 0; q < 4; q++) {
                    unsigned u[4];
                    #pragma unroll
                    for (int e = 0; e < 4; e++) {
                        float2 av = *(const float2*)(fi + q * 8 + 2 * e);
                        float2 bv = *(const float2*)(fj + q * 8 + 2 * e);
                        float v0 = av.x * bv.x, v1 = av.y * bv.y;
                        s += v0 + v1;
                        u[e] = bf2(v0, v1);
                    }
                    *(uint4*)(A + q * 16) = make_uint4(u[0], u[1], u[2], u[3]);
                }
                sSumP[2 * r + dh] = s;
            } else {
                #pragma unroll
                for (int q = 0; q < 4; q++)
                    *(uint4*)(A + q * 16) = make_uint4(0, 0, 0, 0);
            }
        }
        __syncthreads();

        if (tid < MTILE) {
            int p = t * MTILE + tid;
            if (p < NPAIR) ssum[p] = sSumP[2 * tid] + sSumP[2 * tid + 1];
        }

        // -- warp MMA: 16x64 block = 8 n-tiles, K=64 in 4 steps --
        float4 acc[8];
        #pragma unroll
        for (int j = 0; j < 8; j++) acc[j] = make_float4(0.f, 0.f, 0.f, 0.f);

        #pragma unroll
        for (int kk = 0; kk < 4; kk++) {
            unsigned a0, a1, a2, a3;
            ldsm4(a0, a1, a2, a3, aArow + kk * 32);
            #pragma unroll
            for (int jp = 0; jp < 4; jp++) {
                unsigned b0, b1v, b2v, b3;
                ldsm4(b0, b1v, b2v, b3, aBrow + (jp * 16) * BST + kk * 32);
                mma16816(acc[2 * jp],     a0, a1, a2, a3, b0, b1v);
                mma16816(acc[2 * jp + 1], a0, a1, a2, a3, b2v, b3);
            }
        }

        // -- epilogue: relu + dot(w2), quad-reduce, write logits --
        float pl0 = 0.f, pl1 = 0.f;
        #pragma unroll
        for (int j = 0; j < 8; j++) {
            int c0 = j * 8 + (lane & 3) * 2;
            float2 bb = *(const float2*)(sb1 + c0);
            float2 ww = *(const float2*)(sw2 + c0);
            pl0 = fmaf(fmaxf(acc[j].x + bb.x, 0.f), ww.x, pl0);
            pl0 = fmaf(fmaxf(acc[j].y + bb.y, 0.f), ww.y, pl0);
            pl1 = fmaf(fmaxf(acc[j].z + bb.x, 0.f), ww.x, pl1);
            pl1 = fmaf(fmaxf(acc[j].w + bb.y, 0.f), ww.y, pl1);
        }
        #pragma unroll
        for (int o = 1; o <= 2; o <<= 1) {
            pl0 += __shfl_xor_sync(0xffffffffu, pl0, o);
            pl1 += __shfl_xor_sync(0xffffffffu, pl1, o);
        }
        if ((lane & 3) == 0) {
            int p = t * MTILE + m0 + g;
            if (p < NPAIR)     slog[p]     = pl0;
            if (p + 8 < NPAIR) slog[p + 8] = pl1;
        }
    }
    __syncthreads();

    // ---- softmax over pairs + combine ----
    float m = -1e30f;
    for (int p = tid; p < NPAIR; p += NTHREADS) m = fmaxf(m, slog[p]);
    #pragma unroll
    for (int o = 16; o; o >>= 1) m = fmaxf(m, __shfl_xor_sync(0xffffffffu, m, o));
    if (lane == 0) sRed[wid] = m;
    __syncthreads();
    if (tid < 32) {
        float tv = (tid < NTHREADS / 32) ? sRed[tid] : -1e30f;
        #pragma unroll
        for (int o = 4; o; o >>= 1) tv = fmaxf(tv, __shfl_xor_sync(0xffffffffu, tv, o));
        if (tid == 0) sM = tv;
    }
    __syncthreads();
    const float M = sM;

    float es = 0.0f, ws = 0.0f;
    for (int p = tid; p < NPAIR; p += NTHREADS) {
        float e = __expf(slog[p] - M);
        es += e;
        ws = fmaf(e, ssum[p], ws);
    }
    #pragma unroll
    for (int o = 16; o; o >>= 1) {
        es += __shfl_xor_sync(0xffffffffu, es, o);
        ws += __shfl_xor_sync(0xffffffffu, ws, o);
    }
    if (lane == 0) { sRed[wid] = es; sRed[16 + wid] = ws; }
    __syncthreads();
    if (tid == 0) {
        float ES = 0.0f, WS = 0.0f;
        #pragma unroll
        for (int w = 0; w < NTHREADS / 32; w++) { ES += sRed[w]; WS += sRed[16 + w]; }
        float lin = lin_b[0];
        #pragma unroll
        for (int f = 0; f < NF; f++) lin += sLinA[f];
        out[b] = lin + WS / ES;
    }
}

extern "C" void kernel_launch(void* const* d_in, const int* in_sizes, int n_in,
                              void* d_out, int out_size)
{
    const int*   x     = (const int*)d_in[0];
    const float* emb   = (const float*)d_in[1];
    const float* W1    = (const float*)d_in[2];
    const float* b1    = (const float*)d_in[3];
    const float* w2    = (const float*)d_in[4];
    const float* b2    = (const float*)d_in[5];
    const float* lin_w = (const float*)d_in[6];
    const float* lin_b = (const float*)d_in[7];
    float* out = (float*)d_out;

    static int configured = 0;
    if (!configured) {
        cudaFuncSetAttribute(afm_kernel, cudaFuncAttributeMaxDynamicSharedMemorySize,
                             SMEM_DYN);
        configured = 1;
    }
    afm_kernel<<<out_size, NTHREADS, SMEM_DYN>>>(x, emb, W1, b1, w2, b2,
                                                 lin_w, lin_b, out);
}

// round 5
// speedup vs baseline: 5.1397x; 1.1244x over previous
#include <cuda_runtime.h>
#include <cuda_bf16.h>

#define NF    50
#define DIM   64
#define ATT   64
#define CARDI 10000
#define NPAIR 1225
#define NTHREADS 256
#define MTILE 128
#define NTILES 10
#define FST   68          // sF row stride (floats)
#define BST   144         // bf16 tile row stride in BYTES

// ---- dynamic smem byte offsets ----
#define OFF_A    0                       // A tile: 128 rows x 144B
#define OFF_B    (128 * BST)             // B = W1^T: 64 rows x 144B
#define OFF_F    (OFF_B + 64 * BST)      // sF fp32 50*68
#define OFF_LOG  (OFF_F + NF * FST * 4)
#define OFF_SUM  (OFF_LOG + NPAIR * 4)
#define OFF_SP   (OFF_SUM + NPAIR * 4)
#define OFF_SI   (OFF_SP + 256 * 4)
#define OFF_SJ   (OFF_SI + 1232)
#define SMEM_DYN (OFF_SJ + 1232)

__device__ __forceinline__ unsigned smem_u32(const void* p) {
    unsigned a;
    asm("{ .reg .u64 t; cvta.to.shared.u64 t, %1; cvt.u32.u64 %0, t; }"
        : "=r"(a) : "l"(p));
    return a;
}
__device__ __forceinline__ unsigned bf2(float lo, float hi) {
    unsigned r;
    asm("cvt.rn.bf16x2.f32 %0, %1, %2;" : "=r"(r) : "f"(hi), "f"(lo));
    return r;
}
__device__ __forceinline__ void ldsm4(unsigned& r0, unsigned& r1,
                                      unsigned& r2, unsigned& r3, unsigned addr) {
    asm volatile("ldmatrix.sync.aligned.m8n8.x4.shared.b16 {%0,%1,%2,%3}, [%4];"
                 : "=r"(r0), "=r"(r1), "=r"(r2), "=r"(r3) : "r"(addr));
}
__device__ __forceinline__ void mma16816(float4& d,
                                         unsigned a0, unsigned a1, unsigned a2, unsigned a3,
                                         unsigned b0, unsigned b1) {
    asm volatile(
        "mma.sync.aligned.m16n8k16.row.col.f32.bf16.bf16.f32 "
        "{%0,%1,%2,%3}, {%4,%5,%6,%7}, {%8,%9}, {%0,%1,%2,%3};"
        : "+f"(d.x), "+f"(d.y), "+f"(d.z), "+f"(d.w)
        : "r"(a0), "r"(a1), "r"(a2), "r"(a3), "r"(b0), "r"(b1));
}

__global__ __launch_bounds__(NTHREADS, 2)
void afm_kernel(const int* __restrict__ x32,
                const float* __restrict__ emb,
                const float* __restrict__ W1,
                const float* __restrict__ b1,
                const float* __restrict__ w2,
                const float* __restrict__ b2,
                const float* __restrict__ lin_w,
                const float* __restrict__ lin_b,
                float* __restrict__ out)
{
    extern __shared__ __align__(16) char sb[];
    float* sF    = (float*)(sb + OFF_F);
    float* slog  = (float*)(sb + OFF_LOG);
    float* ssum  = (float*)(sb + OFF_SUM);
    float* sSumP = (float*)(sb + OFF_SP);
    unsigned char* si = (unsigned char*)(sb + OFF_SI);
    unsigned char* sj = (unsigned char*)(sb + OFF_SJ);
    const unsigned sbase = smem_u32(sb);

    __shared__ float sb1[ATT], sw2[ATT], sLinA[64], sRed[32], sM;

    const int b = blockIdx.x, tid = threadIdx.x;
    const int wid = tid >> 5, lane = tid & 31;

    // int32 vs int64 index dtype probe (values < 5e5 -> int64 high words zero)
    const bool is64 = (x32[1] == 0) & (x32[3] == 0) & (x32[5] == 0) & (x32[7] == 0);
    const long long* x64 = (const long long*)x32;

    // ---- Phase A: stage embeddings fp32, B = W1^T bf16, biases, pair tables ----
    for (int q = tid; q < NF * DIM / 4; q += NTHREADS) {
        int row = q >> 4, c4 = q & 15;
        long long xv = is64 ? x64[(long long)b * NF + row]
                            : (long long)x32[b * NF + row];
        int gidx = (int)xv + row * CARDI;
        float4 v = ((const float4*)(emb + (long long)gidx * DIM))[c4];
        *(float4*)(sF + row * FST + c4 * 4) = v;
    }
    {   // B[n][k] = W1[k][n] bf16, row stride 144B
        int n = tid & 63, kg = tid >> 6;
        unsigned u[8];
        #pragma unroll
        for (int e = 0; e < 8; e++) {
            float w0 = W1[(kg * 16 + 2 * e) * ATT + n];
            float w1v = W1[(kg * 16 + 2 * e + 1) * ATT + n];
            u[e] = bf2(w0, w1v);
        }
        char* dst = sb + OFF_B + n * BST + kg * 32;
        *(uint4*)(dst)      = make_uint4(u[0], u[1], u[2], u[3]);
        *(uint4*)(dst + 16) = make_uint4(u[4], u[5], u[6], u[7]);
    }
    if (tid < ATT) { sb1[tid] = b1[tid]; sw2[tid] = w2[tid]; }
    if (tid < 64) sLinA[tid] = 0.0f;
    if (tid < NF) {
        long long xv = is64 ? x64[(long long)b * NF + tid]
                            : (long long)x32[b * NF + tid];
        sLinA[tid] = lin_w[(int)xv + tid * CARDI];
    }
    for (int p = tid; p < NPAIR; p += NTHREADS) {
        int i = (int)((99.0f - sqrtf(9801.0f - 8.0f * (float)p)) * 0.5f);
        i = min(max(i, 0), 48);
        while (i * (99 - i) / 2 > p) --i;
        while ((i + 1) * (98 - i) / 2 <= p) ++i;
        si[p] = (unsigned char)i;
        sj[p] = (unsigned char)(i + 1 + (p - i * (99 - i) / 2));
    }

    const int m0 = wid * 16;
    const int g  = lane >> 2;
    const unsigned aArow = sbase + OFF_A + (m0 + (lane & 15)) * BST + (lane >> 4) * 16;
    const unsigned aBrow = sbase + OFF_B + ((lane >> 4) * 8 + (lane & 7)) * BST
                                 + ((lane >> 3) & 1) * 16;
    __syncthreads();

    // ---- preload ALL B fragments into registers (invariant across tiles) ----
    unsigned Bf[4][4][4];            // [k-step][jp][frag]
    #pragma unroll
    for (int kk = 0; kk < 4; kk++)
        #pragma unroll
        for (int jp = 0; jp < 4; jp++)
            ldsm4(Bf[kk][jp][0], Bf[kk][jp][1], Bf[kk][jp][2], Bf[kk][jp][3],
                  aBrow + (jp * 16) * BST + kk * 32);

    // ---- tiles ----
    for (int t = 0; t < NTILES; t++) {
        __syncthreads();   // previous tile's A reads done

        // -- build bf16 A tile (float4 loads) + fp32 inter_sum partials --
        {
            int r = tid >> 1, dh = tid & 1;       // 32 k's per (r,dh)
            int p = t * MTILE + r;
            char* A = sb + OFF_A + r * BST + dh * 64;
            if (p < NPAIR) {
                const float4* fi = (const float4*)(sF + si[p] * FST + dh * 32);
                const float4* fj = (const float4*)(sF + sj[p] * FST + dh * 32);
                float s = 0.0f;
                #pragma unroll
                for (int q = 0; q < 4; q++) {
                    float4 a0 = fi[2 * q],     b0 = fj[2 * q];
                    float4 a1 = fi[2 * q + 1], b1v = fj[2 * q + 1];
                    float v0 = a0.x * b0.x, v1 = a0.y * b0.y;
                    float v2 = a0.z * b0.z, v3 = a0.w * b0.w;
                    float v4 = a1.x * b1v.x, v5 = a1.y * b1v.y;
                    float v6 = a1.z * b1v.z, v7 = a1.w * b1v.w;
                    s += (v0 + v1) + (v2 + v3) + (v4 + v5) + (v6 + v7);
                    *(uint4*)(A + q * 16) =
                        make_uint4(bf2(v0, v1), bf2(v2, v3), bf2(v4, v5), bf2(v6, v7));
                }
                sSumP[2 * r + dh] = s;
            } else {
                #pragma unroll
                for (int q = 0; q < 4; q++)
                    *(uint4*)(A + q * 16) = make_uint4(0, 0, 0, 0);
            }
        }
        __syncthreads();

        if (tid < MTILE) {
            int p = t * MTILE + tid;
            if (p < NPAIR) ssum[p] = sSumP[2 * tid] + sSumP[2 * tid + 1];
        }

        // -- warp MMA: 16x64 block, B from registers --
        float4 acc[8];
        #pragma unroll
        for (int j = 0; j < 8; j++) acc[j] = make_float4(0.f, 0.f, 0.f, 0.f);

        #pragma unroll
        for (int kk = 0; kk < 4; kk++) {
            unsigned a0, a1, a2, a3;
            ldsm4(a0, a1, a2, a3, aArow + kk * 32);
            #pragma unroll
            for (int jp = 0; jp < 4; jp++) {
                mma16816(acc[2 * jp],     a0, a1, a2, a3, Bf[kk][jp][0], Bf[kk][jp][1]);
                mma16816(acc[2 * jp + 1], a0, a1, a2, a3, Bf[kk][jp][2], Bf[kk][jp][3]);
            }
        }

        // -- epilogue: relu + dot(w2), quad-reduce, write logits --
        float pl0 = 0.f, pl1 = 0.f;
        #pragma unroll
        for (int j = 0; j < 8; j++) {
            int c0 = j * 8 + (lane & 3) * 2;
            float2 bb = *(const float2*)(sb1 + c0);
            float2 ww = *(const float2*)(sw2 + c0);
            pl0 = fmaf(fmaxf(acc[j].x + bb.x, 0.f), ww.x, pl0);
            pl0 = fmaf(fmaxf(acc[j].y + bb.y, 0.f), ww.y, pl0);
            pl1 = fmaf(fmaxf(acc[j].z + bb.x, 0.f), ww.x, pl1);
            pl1 = fmaf(fmaxf(acc[j].w + bb.y, 0.f), ww.y, pl1);
        }
        #pragma unroll
        for (int o = 1; o <= 2; o <<= 1) {
            pl0 += __shfl_xor_sync(0xffffffffu, pl0, o);
            pl1 += __shfl_xor_sync(0xffffffffu, pl1, o);
        }
        if ((lane & 3) == 0) {
            int p = t * MTILE + m0 + g;
            if (p < NPAIR)     slog[p]     = pl0;
            if (p + 8 < NPAIR) slog[p + 8] = pl1;
        }
    }
    __syncthreads();

    // ---- softmax over pairs + combine ----
    float m = -1e30f;
    for (int p = tid; p < NPAIR; p += NTHREADS) m = fmaxf(m, slog[p]);
    #pragma unroll
    for (int o = 16; o; o >>= 1) m = fmaxf(m, __shfl_xor_sync(0xffffffffu, m, o));
    if (lane == 0) sRed[wid] = m;
    __syncthreads();
    if (tid < 32) {
        float tv = (tid < NTHREADS / 32) ? sRed[tid] : -1e30f;
        #pragma unroll
        for (int o = 4; o; o >>= 1) tv = fmaxf(tv, __shfl_xor_sync(0xffffffffu, tv, o));
        if (tid == 0) sM = tv;
    }
    __syncthreads();
    const float M = sM;

    float es = 0.0f, ws = 0.0f;
    for (int p = tid; p < NPAIR; p += NTHREADS) {
        float e = __expf(slog[p] - M);
        es += e;
        ws = fmaf(e, ssum[p], ws);
    }
    #pragma unroll
    for (int o = 16; o; o >>= 1) {
        es += __shfl_xor_sync(0xffffffffu, es, o);
        ws += __shfl_xor_sync(0xffffffffu, ws, o);
    }
    if (lane == 0) { sRed[wid] = es; sRed[16 + wid] = ws; }
    __syncthreads();
    if (tid == 0) {
        float ES = 0.0f, WS = 0.0f;
        #pragma unroll
        for (int w = 0; w < NTHREADS / 32; w++) { ES += sRed[w]; WS += sRed[16 + w]; }
        float lin = lin_b[0];
        #pragma unroll
        for (int f = 0; f < NF; f++) lin += sLinA[f];
        out[b] = lin + WS / ES;
    }
}

extern "C" void kernel_launch(void* const* d_in, const int* in_sizes, int n_in,
                              void* d_out, int out_size)
{
    const int*   x     = (const int*)d_in[0];
    const float* emb   = (const float*)d_in[1];
    const float* W1    = (const float*)d_in[2];
    const float* b1    = (const float*)d_in[3];
    const float* w2    = (const float*)d_in[4];
    const float* b2    = (const float*)d_in[5];
    const float* lin_w = (const float*)d_in[6];
    const float* lin_b = (const float*)d_in[7];
    float* out = (float*)d_out;

    static int configured = 0;
    if (!configured) {
        cudaFuncSetAttribute(afm_kernel, cudaFuncAttributeMaxDynamicSharedMemorySize,
                             SMEM_DYN);
        configured = 1;
    }
    afm_kernel<<<out_size, NTHREADS, SMEM_DYN>>>(x, emb, W1, b1, w2, b2,
                                                 lin_w, lin_b, out);
}

// round 6
// speedup vs baseline: 6.8585x; 1.3344x over previous
#include <cuda_runtime.h>
#include <cuda_bf16.h>

#define NF    50
#define DIM   64
#define ATT   64
#define CARDI 10000
#define NPAIR 1225
#define NTHREADS 256
#define MTILE 128
#define NTILES 10
#define BST   144         // bf16 tile row stride in BYTES
#define FSTB  144         // sF (bf16) row stride in BYTES

// ---- dynamic smem byte offsets ----
#define OFF_A0   0                       // A tile buf0: 128 x 144B
#define OFF_A1   (128 * BST)             // A tile buf1
#define OFF_B    (2 * 128 * BST)         // B = W1^T: 64 x 144B
#define OFF_F    (OFF_B + 64 * BST)      // sF bf16: 50 x 144B
#define OFF_LOG  (OFF_F + NF * FSTB)
#define OFF_SUM  (OFF_LOG + NPAIR * 4)
#define OFF_SI   (OFF_SUM + NPAIR * 4)
#define OFF_SJ   (OFF_SI + 1232)
#define SMEM_DYN (OFF_SJ + 1232)

__device__ __forceinline__ unsigned smem_u32(const void* p) {
    unsigned a;
    asm("{ .reg .u64 t; cvta.to.shared.u64 t, %1; cvt.u32.u64 %0, t; }"
        : "=r"(a) : "l"(p));
    return a;
}
__device__ __forceinline__ unsigned bf2(float lo, float hi) {
    unsigned r;
    asm("cvt.rn.bf16x2.f32 %0, %1, %2;" : "=r"(r) : "f"(hi), "f"(lo));
    return r;
}
__device__ __forceinline__ unsigned hmul2(unsigned a, unsigned b) {
    unsigned r;
    asm("mul.rn.bf16x2 %0, %1, %2;" : "=r"(r) : "r"(a), "r"(b));
    return r;
}
__device__ __forceinline__ void ldsm4(unsigned& r0, unsigned& r1,
                                      unsigned& r2, unsigned& r3, unsigned addr) {
    asm volatile("ldmatrix.sync.aligned.m8n8.x4.shared.b16 {%0,%1,%2,%3}, [%4];"
                 : "=r"(r0), "=r"(r1), "=r"(r2), "=r"(r3) : "r"(addr));
}
__device__ __forceinline__ void mma16816(float4& d,
                                         unsigned a0, unsigned a1, unsigned a2, unsigned a3,
                                         unsigned b0, unsigned b1) {
    asm volatile(
        "mma.sync.aligned.m16n8k16.row.col.f32.bf16.bf16.f32 "
        "{%0,%1,%2,%3}, {%4,%5,%6,%7}, {%8,%9}, {%0,%1,%2,%3};"
        : "+f"(d.x), "+f"(d.y), "+f"(d.z), "+f"(d.w)
        : "r"(a0), "r"(a1), "r"(a2), "r"(a3), "r"(b0), "r"(b1));
}

__global__ __launch_bounds__(NTHREADS, 2)
void afm_kernel(const int* __restrict__ x32,
                const float* __restrict__ emb,
                const float* __restrict__ W1,
                const float* __restrict__ b1,
                const float* __restrict__ w2,
                const float* __restrict__ b2,
                const float* __restrict__ lin_w,
                const float* __restrict__ lin_b,
                float* __restrict__ out)
{
    extern __shared__ __align__(16) char sb[];
    float* slog  = (float*)(sb + OFF_LOG);
    float* ssum  = (float*)(sb + OFF_SUM);
    unsigned char* si = (unsigned char*)(sb + OFF_SI);
    unsigned char* sj = (unsigned char*)(sb + OFF_SJ);
    const unsigned sbase = smem_u32(sb);

    __shared__ float sb1[ATT], sw2[ATT], sLinA[64], sRed[32], sM;

    const int b = blockIdx.x, tid = threadIdx.x;
    const int wid = tid >> 5, lane = tid & 31;

    // int32 vs int64 index dtype probe (values < 5e5 -> int64 high words zero)
    const bool is64 = (x32[1] == 0) & (x32[3] == 0) & (x32[5] == 0) & (x32[7] == 0);
    const long long* x64 = (const long long*)x32;

    // ---- Phase A: stage embeddings (bf16), B = W1^T bf16, biases, tables ----
    for (int q = tid; q < NF * DIM / 4; q += NTHREADS) {
        int row = q >> 4, c4 = q & 15;
        long long xv = is64 ? x64[(long long)b * NF + row]
                            : (long long)x32[b * NF + row];
        int gidx = (int)xv + row * CARDI;
        float4 v = ((const float4*)(emb + (long long)gidx * DIM))[c4];
        uint2 o = make_uint2(bf2(v.x, v.y), bf2(v.z, v.w));
        *(uint2*)(sb + OFF_F + row * FSTB + c4 * 8) = o;
    }
    {   // B[n][k] = W1[k][n] bf16, row stride 144B
        int n = tid & 63, kg = tid >> 6;
        unsigned u[8];
        #pragma unroll
        for (int e = 0; e < 8; e++) {
            float w0 = W1[(kg * 16 + 2 * e) * ATT + n];
            float w1v = W1[(kg * 16 + 2 * e + 1) * ATT + n];
            u[e] = bf2(w0, w1v);
        }
        char* dst = sb + OFF_B + n * BST + kg * 32;
        *(uint4*)(dst)      = make_uint4(u[0], u[1], u[2], u[3]);
        *(uint4*)(dst + 16) = make_uint4(u[4], u[5], u[6], u[7]);
    }
    if (tid < ATT) { sb1[tid] = b1[tid]; sw2[tid] = w2[tid]; }
    if (tid < 64) sLinA[tid] = 0.0f;
    if (tid < NF) {
        long long xv = is64 ? x64[(long long)b * NF + tid]
                            : (long long)x32[b * NF + tid];
        sLinA[tid] = lin_w[(int)xv + tid * CARDI];
    }
    for (int p = tid; p < NPAIR; p += NTHREADS) {
        int i = (int)((99.0f - sqrtf(9801.0f - 8.0f * (float)p)) * 0.5f);
        i = min(max(i, 0), 48);
        while (i * (99 - i) / 2 > p) --i;
        while ((i + 1) * (98 - i) / 2 <= p) ++i;
        si[p] = (unsigned char)i;
        sj[p] = (unsigned char)(i + 1 + (p - i * (99 - i) / 2));
    }

    const int m0 = wid * 16;
    const int g  = lane >> 2;
    const unsigned aArow0 = sbase + OFF_A0 + (m0 + (lane & 15)) * BST + (lane >> 4) * 16;
    const unsigned aArow1 = aArow0 + (OFF_A1 - OFF_A0);
    const unsigned aBrow  = sbase + OFF_B + ((lane >> 4) * 8 + (lane & 7)) * BST
                                  + ((lane >> 3) & 1) * 16;
    // ones-column B fragment (n_tile=0 all-ones): lanes with n=lane>>2==0 hold 1.0
    const unsigned onesf = (lane < 4) ? 0x3F803F80u : 0u;

    __syncthreads();

    // ---- preload all B fragments (invariant across tiles) ----
    unsigned Bf[4][4][4];
    #pragma unroll
    for (int kk = 0; kk < 4; kk++)
        #pragma unroll
        for (int jp = 0; jp < 4; jp++)
            ldsm4(Bf[kk][jp][0], Bf[kk][jp][1], Bf[kk][jp][2], Bf[kk][jp][3],
                  aBrow + (jp * 16) * BST + kk * 32);

    // ---- tiles: build A(t) into buf[t&1]; sync; MMA+epilogue(t) ----
    for (int t = 0; t < NTILES; t++) {
        const int abuf = (t & 1) ? OFF_A1 : OFF_A0;
        {
            int r = tid >> 1, dh = tid & 1;       // 32 k's (64B) per (r,dh)
            int p = t * MTILE + r;
            char* A = sb + abuf + r * BST + dh * 64;
            if (p < NPAIR) {
                const uint4* fi = (const uint4*)(sb + OFF_F + si[p] * FSTB + dh * 64);
                const uint4* fj = (const uint4*)(sb + OFF_F + sj[p] * FSTB + dh * 64);
                #pragma unroll
                for (int q = 0; q < 4; q++) {
                    uint4 a = fi[q], c = fj[q];
                    *(uint4*)(A + q * 16) = make_uint4(hmul2(a.x, c.x), hmul2(a.y, c.y),
                                                       hmul2(a.z, c.z), hmul2(a.w, c.w));
                }
            } else {
                #pragma unroll
                for (int q = 0; q < 4; q++)
                    *(uint4*)(A + q * 16) = make_uint4(0, 0, 0, 0);
            }
        }
        __syncthreads();

        // -- warp MMA: 16x64 block + ones-column for inter_sum --
        float4 acc[8];
        float4 accS = make_float4(0.f, 0.f, 0.f, 0.f);
        #pragma unroll
        for (int j = 0; j < 8; j++) acc[j] = make_float4(0.f, 0.f, 0.f, 0.f);

        const unsigned aA = (t & 1) ? aArow1 : aArow0;
        #pragma unroll
        for (int kk = 0; kk < 4; kk++) {
            unsigned a0, a1, a2, a3;
            ldsm4(a0, a1, a2, a3, aA + kk * 32);
            #pragma unroll
            for (int jp = 0; jp < 4; jp++) {
                mma16816(acc[2 * jp],     a0, a1, a2, a3, Bf[kk][jp][0], Bf[kk][jp][1]);
                mma16816(acc[2 * jp + 1], a0, a1, a2, a3, Bf[kk][jp][2], Bf[kk][jp][3]);
            }
            mma16816(accS, a0, a1, a2, a3, onesf, onesf);
        }

        // -- epilogue: relu + dot(w2), quad-reduce; logits + inter_sum --
        float pl0 = 0.f, pl1 = 0.f;
        #pragma unroll
        for (int j = 0; j < 8; j++) {
            int c0 = j * 8 + (lane & 3) * 2;
            float2 bb = *(const float2*)(sb1 + c0);
            float2 ww = *(const float2*)(sw2 + c0);
            pl0 = fmaf(fmaxf(acc[j].x + bb.x, 0.f), ww.x, pl0);
            pl0 = fmaf(fmaxf(acc[j].y + bb.y, 0.f), ww.y, pl0);
            pl1 = fmaf(fmaxf(acc[j].z + bb.x, 0.f), ww.x, pl1);
            pl1 = fmaf(fmaxf(acc[j].w + bb.y, 0.f), ww.y, pl1);
        }
        #pragma unroll
        for (int o = 1; o <= 2; o <<= 1) {
            pl0 += __shfl_xor_sync(0xffffffffu, pl0, o);
            pl1 += __shfl_xor_sync(0xffffffffu, pl1, o);
        }
        if ((lane & 3) == 0) {
            int p = t * MTILE + m0 + g;
            if (p < NPAIR)     { slog[p]     = pl0; ssum[p]     = accS.x; }
            if (p + 8 < NPAIR) { slog[p + 8] = pl1; ssum[p + 8] = accS.z; }
        }
    }
    __syncthreads();

    // ---- softmax over pairs + combine ----
    float m = -1e30f;
    for (int p = tid; p < NPAIR; p += NTHREADS) m = fmaxf(m, slog[p]);
    #pragma unroll
    for (int o = 16; o; o >>= 1) m = fmaxf(m, __shfl_xor_sync(0xffffffffu, m, o));
    if (lane == 0) sRed[wid] = m;
    __syncthreads();
    if (tid < 32) {
        float tv = (tid < NTHREADS / 32) ? sRed[tid] : -1e30f;
        #pragma unroll
        for (int o = 4; o; o >>= 1) tv = fmaxf(tv, __shfl_xor_sync(0xffffffffu, tv, o));
        if (tid == 0) sM = tv;
    }
    __syncthreads();
    const float M = sM;

    float es = 0.0f, ws = 0.0f;
    for (int p = tid; p < NPAIR; p += NTHREADS) {
        float e = __expf(slog[p] - M);
        es += e;
        ws = fmaf(e, ssum[p], ws);
    }
    #pragma unroll
    for (int o = 16; o; o >>= 1) {
        es += __shfl_xor_sync(0xffffffffu, es, o);
        ws += __shfl_xor_sync(0xffffffffu, ws, o);
    }
    if (lane == 0) { sRed[wid] = es; sRed[16 + wid] = ws; }
    __syncthreads();
    if (tid == 0) {
        float ES = 0.0f, WS = 0.0f;
        #pragma unroll
        for (int w = 0; w < NTHREADS / 32; w++) { ES += sRed[w]; WS += sRed[16 + w]; }
        float lin = lin_b[0];
        #pragma unroll
        for (int f = 0; f < NF; f++) lin += sLinA[f];
        out[b] = lin + WS / ES;
    }
}

extern "C" void kernel_launch(void* const* d_in, const int* in_sizes, int n_in,
                              void* d_out, int out_size)
{
    const int*   x     = (const int*)d_in[0];
    const float* emb   = (const float*)d_in[1];
    const float* W1    = (const float*)d_in[2];
    const float* b1    = (const float*)d_in[3];
    const float* w2    = (const float*)d_in[4];
    const float* b2    = (const float*)d_in[5];
    const float* lin_w = (const float*)d_in[6];
    const float* lin_b = (const float*)d_in[7];
    float* out = (float*)d_out;

    static int configured = 0;
    if (!configured) {
        cudaFuncSetAttribute(afm_kernel, cudaFuncAttributeMaxDynamicSharedMemorySize,
                             SMEM_DYN);
        configured = 1;
    }
    afm_kernel<<<out_size, NTHREADS, SMEM_DYN>>>(x, emb, W1, b1, w2, b2,
                                                 lin_w, lin_b, out);
}